// round 13
// baseline (speedup 1.0000x reference)
#include <cuda_runtime.h>
#include <math.h>
#include <float.h>

// Shapes: B=8, N=512, T=64, D=128, E=32, M=3, k_top=25
#define KTOP 25

// ---------------- scratch (__device__ globals; allocation is forbidden) ----------------
__device__ float g_uv[2 * 384];            // u = W_ih@proj_W ; v = W_ih@proj_b + b_ih
__device__ float g_qn[3 * 32 * 128];       // normalized queries [m][e][d]
__device__ float g_H[4096 * 128];          // final GRU hidden state [b*512+n][d]
__device__ float g_hw[4096];               // h . out_W
__device__ float g_zpw[4096];              // prior @ hw
__device__ float g_part[8 * 16 * 256];     // per-(b,chunk) partial [sum(128) | sumsq(128)]
__device__ float g_probs[8 * 3];
__device__ float g_scores[8 * 3 * 32 * 512];   // [b][m][e][n]
__device__ float g_Hmix[8 * 32 * 512];         // [b][e][n]

// ---------------- helpers ----------------
__device__ __forceinline__ unsigned long long pk2(float lo, float hi) {
    unsigned long long r;
    asm("mov.b64 %0,{%1,%2};" : "=l"(r) : "f"(lo), "f"(hi));
    return r;
}
__device__ __forceinline__ void upk2(unsigned long long v, float& lo, float& hi) {
    asm("mov.b64 {%0,%1},%2;" : "=f"(lo), "=f"(hi) : "l"(v));
}
#define FMA2(acc, a, b) asm("fma.rn.f32x2 %0,%1,%2,%0;" : "+l"(acc) : "l"(a), "l"(b))

__device__ __forceinline__ float sigm(float x) { return 1.0f / (1.0f + __expf(-x)); }
__device__ __forceinline__ float tanh_f(float x) {
    float t = __expf(-2.0f * x);
    return (1.0f - t) / (1.0f + t);
}
__device__ __forceinline__ float warp_sum(float v) {
#pragma unroll
    for (int off = 16; off; off >>= 1) v += __shfl_xor_sync(0xFFFFFFFFu, v, off);
    return v;
}

// ---------------- K0a: u = W_ih@proj_W, v = W_ih@proj_b + b_ih ----------------
__global__ void k_prep_uv(const float* __restrict__ Wih, const float* __restrict__ pW,
                          const float* __restrict__ pb, const float* __restrict__ bih) {
    int tid = threadIdx.x;
    if (tid < 384) {
        float su = 0.f, sv = 0.f;
        for (int d = 0; d < 128; d++) {
            float w = Wih[tid * 128 + d];
            su = fmaf(w, pW[d], su);
            sv = fmaf(w, pb[d], sv);
        }
        g_uv[tid] = su;
        g_uv[384 + tid] = sv + bih[tid];
    }
}

// ---------------- K0b: normalize queries (warp per row, 96 rows) ----------------
__global__ void k_prep_q(const float* __restrict__ q) {
    int w = threadIdx.x >> 5, lane = threadIdx.x & 31;
#pragma unroll
    for (int rr = 0; rr < 4; rr++) {
        int row = (blockIdx.x * 8 + w) * 4 + rr;  // 0..95
        float4 v = ((const float4*)(q + row * 128))[lane];
        float ss = v.x * v.x + v.y * v.y + v.z * v.z + v.w * v.w;
        ss = warp_sum(ss);
        float inv = 1.0f / fmaxf(sqrtf(ss), 1e-12f);
        float4 o = make_float4(v.x * inv, v.y * inv, v.z * inv, v.w * inv);
        ((float4*)(g_qn + row * 128))[lane] = o;
    }
}

// ---------------- K0c: zero Hmix ----------------
__global__ void k_zero() {
    int base = blockIdx.x * 256 + threadIdx.x;  // grid 128 x 256 = 32768
#pragma unroll
    for (int i = 0; i < 4; i++) g_Hmix[base + i * 32768] = 0.f;
}

// ---------------- K1: GRU (hot kernel) ----------------
// 128 CTAs x 1024 threads, 32 sequences per CTA, k-dimension split in half.
// Thread = (sp = lane&15 -> seqs {2sp,2sp+1}, khalf = lane>>4, dtile = warp).
// W_hh persistent in SMEM, gate-interleaved Wt[k][d*3+g], row stride 388 floats,
// with the khalf=1 half-matrix shifted +4 floats so the two broadcast groups of
// each LDS.128 land in disjoint bank quads (1 wavefront, no conflict).
// Packed f32x2 FMA inner product; shfl.bfly(16) reduces the two k-halves.
#define WSTR 388

__global__ __launch_bounds__(1024, 1) void k_gru(const float* __restrict__ Whh,
                                                 const float* __restrict__ bhh,
                                                 const float* __restrict__ x) {
    extern __shared__ float sm[];
    float* Wt = sm;                         // 128*388 + 4
    float* hb = Wt + (128 * WSTR + 4);      // h[d][32 seqs]
    float* ssh = hb + 4096;                 // s staged [t][seq] : 64*32
    float* tu = ssh + 2048;                 // u[o], o = g*128+d   (384)
    float* tc = tu + 384;                   // g<2: v+bh ; g==2: bh_n (384)
    float* tv2 = tc + 384;                  // v_n[d] (128)

    const int tid = threadIdx.x;
    const int w = tid >> 5, lane = tid & 31;
    const int sp = lane & 15;               // seq pair: seqs 2sp, 2sp+1
    const int khalf = lane >> 4;            // 0: k in [0,64), 1: k in [64,128)
    const int dbase = w * 4;                // 0..124
    const int i0 = blockIdx.x * 32;

    // stage W_hh transposed + gate-interleaved (+4-float skew for high half)
    for (int idx = tid; idx < 384 * 128; idx += 1024) {
        int o = idx >> 7, k = idx & 127;
        int g = o >> 7, d = o & 127;
        Wt[k * WSTR + ((k >> 6) << 2) + d * 3 + g] = Whh[idx];
    }
    // gather scalar input via the scrambled-reshape map:
    // s(i,t) = x[(i>>9)*32768 + ((i&7)*64 + t)*64 + ((i>>3)&63)]
    for (int idx = tid; idx < 2048; idx += 1024) {
        int ss = idx >> 6, t = idx & 63;
        int i = i0 + ss;
        ssh[t * 32 + ss] = x[(i >> 9) * 32768 + ((i & 7) * 64 + t) * 64 + ((i >> 3) & 63)];
    }
    for (int idx = tid; idx < 4096; idx += 1024) hb[idx] = 0.f;
    // gate-constant tables
    if (tid < 384) {
        int g = tid >> 7;
        tu[tid] = g_uv[tid];
        tc[tid] = (g < 2) ? (g_uv[384 + tid] + bhh[tid]) : bhh[tid];
    }
    if (tid >= 512 && tid < 640) tv2[tid - 512] = g_uv[384 + 256 + (tid - 512)];

    float hreg[8];
#pragma unroll
    for (int q = 0; q < 8; q++) hreg[q] = 0.f;
    __syncthreads();

    const float2* hptr = (const float2*)(hb + khalf * 2048) + sp;
    const ulonglong2* wbase =
        (const ulonglong2*)(Wt + khalf * (64 * WSTR + 4) + dbase * 3);

    for (int t = 0; t < 64; t++) {
        unsigned long long acc[12];
#pragma unroll
        for (int q = 0; q < 12; q++) acc[q] = 0ULL;

        const ulonglong2* wp = wbase;
#pragma unroll 4
        for (int kk = 0; kk < 64; kk++) {
            float2 hv = hptr[kk * 16];
            unsigned long long a0 = pk2(hv.x, hv.x);
            unsigned long long a1 = pk2(hv.y, hv.y);
            ulonglong2 b0 = wp[0], b1 = wp[1], b2 = wp[2];
            unsigned long long bb[6] = {b0.x, b0.y, b1.x, b1.y, b2.x, b2.y};
#pragma unroll
            for (int p = 0; p < 6; p++) {
                FMA2(acc[p], a0, bb[p]);
                FMA2(acc[6 + p], a1, bb[p]);
            }
            wp += WSTR / 4;
        }

        // unpack + cross-k-half reduction (lane ^ 16)
        float f[24];
#pragma unroll
        for (int p = 0; p < 6; p++) {
            upk2(acc[p], f[2 * p], f[2 * p + 1]);
            upk2(acc[6 + p], f[12 + 2 * p], f[13 + 2 * p]);
        }
#pragma unroll
        for (int i = 0; i < 24; i++) f[i] += __shfl_xor_sync(0xFFFFFFFFu, f[i], 16);

        float sv0 = ssh[t * 32 + 2 * sp];
        float sv1 = ssh[t * 32 + 2 * sp + 1];

        float hnew[8];
#pragma unroll
        for (int j = 0; j < 2; j++) {
            float s = j ? sv1 : sv0;
#pragma unroll
            for (int dd = 0; dd < 4; dd++) {
                int base = j * 12 + dd * 3;
                int d = dbase + dd;
                float gr = f[base + 0] + tc[d] + s * tu[d];
                float gz = f[base + 1] + tc[128 + d] + s * tu[128 + d];
                float hn = f[base + 2] + tc[256 + d];
                float gn = fmaf(s, tu[256 + d], tv2[d]);
                float r = sigm(gr), z = sigm(gz);
                float ng = tanh_f(fmaf(r, hn, gn));
                float ho = hreg[j * 4 + dd];
                hnew[j * 4 + dd] = fmaf(z, ho - ng, ng);  // (1-z)*ng + z*h
            }
        }
        __syncthreads();
        if (khalf == 0) {
#pragma unroll
            for (int dd = 0; dd < 4; dd++)
                *((float2*)(hb + (dbase + dd) * 32) + sp) =
                    make_float2(hnew[dd], hnew[4 + dd]);
        }
#pragma unroll
        for (int q = 0; q < 8; q++) hreg[q] = hnew[q];
        __syncthreads();
    }

    for (int idx = tid; idx < 4096; idx += 1024) {
        int s = idx >> 7, d = idx & 127;
        g_H[(i0 + s) * 128 + d] = hb[d * 32 + s];
    }
}

// ---------------- K2: hw = h.out_W + partial router stats (grid 8x16) ----------------
__global__ void k_hw_stats(const float* __restrict__ outW) {
    int b = blockIdx.x >> 4, c = blockIdx.x & 15;
    int n0 = c * 32;
    int tid = threadIdx.x, w = tid >> 5, lane = tid & 31;
    __shared__ float ps0[256], ps1[256];

    float4 ow = ((const float4*)outW)[lane];
#pragma unroll
    for (int p = 0; p < 4; p++) {
        int n = n0 + w + 8 * p;
        float4 hv = ((const float4*)(g_H + (b * 512 + n) * 128))[lane];
        float acc = hv.x * ow.x + hv.y * ow.y + hv.z * ow.z + hv.w * ow.w;
        acc = warp_sum(acc);
        if (lane == 0) g_hw[b * 512 + n] = acc;
    }

    int d = tid & 127, half = tid >> 7;
    float s0 = 0.f, s1 = 0.f;
    for (int nn = half * 16; nn < half * 16 + 16; nn++) {
        float v = g_H[(b * 512 + n0 + nn) * 128 + d];
        s0 += v;
        s1 = fmaf(v, v, s1);
    }
    ps0[tid] = s0;
    ps1[tid] = s1;
    __syncthreads();
    if (tid < 128) {
        g_part[(b * 16 + c) * 256 + tid] = ps0[tid] + ps0[tid + 128];
        g_part[(b * 16 + c) * 256 + 128 + tid] = ps1[tid] + ps1[tid + 128];
    }
}

// ---------------- K3: router probs from partials (grid 8) ----------------
__global__ void k_router(const float* __restrict__ rW, const float* __restrict__ rb,
                         float* __restrict__ dout) {
    int b = blockIdx.x, tid = threadIdx.x;
    __shared__ float mean_s[128], sd_s[128], lg[3];
    {
        int d = tid & 127, which = tid >> 7;
        float s = 0.f;
        for (int c = 0; c < 16; c++) s += g_part[(b * 16 + c) * 256 + which * 128 + d];
        if (which == 0) mean_s[d] = s * (1.0f / 512.0f);
        else sd_s[d] = s;  // sumsq (temp)
    }
    __syncthreads();
    if (tid < 128) {
        float mu = mean_s[tid];
        float var = (sd_s[tid] - 512.0f * mu * mu) * (1.0f / 511.0f);
        sd_s[tid] = sqrtf(fmaxf(var, 0.f));
    }
    __syncthreads();
    if (tid < 3) {
        float a = rb[tid];
        for (int k = 0; k < 128; k++) a = fmaf(mean_s[k], rW[tid * 256 + k], a);
        for (int k = 0; k < 128; k++) a = fmaf(sd_s[k], rW[tid * 256 + 128 + k], a);
        lg[tid] = a;
    }
    __syncthreads();
    if (tid == 0) {
        float mx = fmaxf(lg[0], fmaxf(lg[1], lg[2]));
        float e0 = __expf(lg[0] - mx), e1 = __expf(lg[1] - mx), e2 = __expf(lg[2] - mx);
        float inv = 1.0f / (e0 + e1 + e2);
        g_probs[b * 3 + 0] = e0 * inv;
        g_probs[b * 3 + 1] = e1 * inv;
        g_probs[b * 3 + 2] = e2 * inv;
        dout[4096 + b * 3 + 0] = e0 * inv;
        dout[4096 + b * 3 + 1] = e1 * inv;
        dout[4096 + b * 3 + 2] = e2 * inv;
    }
}

// ---------------- K4: zpw[b,n] = sum_j prior[n,j]*hw[b,j] (grid 512) ----------------
__global__ void k_prior(const float* __restrict__ prior) {
    __shared__ float prow[512];
    __shared__ float red[8][8];  // [warp][b]
    int n = blockIdx.x, tid = threadIdx.x, w = tid >> 5, lane = tid & 31;
    for (int j = tid; j < 512; j += 256) prow[j] = prior[n * 512 + j];
    __syncthreads();
    int j0 = tid * 2;
    float p0 = prow[j0], p1 = prow[j0 + 1];
#pragma unroll
    for (int b = 0; b < 8; b++) {
        float acc = p0 * g_hw[b * 512 + j0] + p1 * g_hw[b * 512 + j0 + 1];
        acc = warp_sum(acc);
        if (lane == 0) red[w][b] = acc;
    }
    __syncthreads();
    if (tid < 8) {
        float s = 0.f;
#pragma unroll
        for (int ww = 0; ww < 8; ww++) s += red[ww][tid];
        g_zpw[tid * 512 + n] = s;
    }
}

// ---------------- K5: scores[b,m,e,n] = norm(h@spW[m]^T + spb[m]) . qn[m,e] --------
__global__ __launch_bounds__(256) void k_scores(const float* __restrict__ spW,
                                                const float* __restrict__ spb) {
    extern __shared__ float sm4[];
    float* W_s = sm4;                    // [128][129]
    float* qn_s = W_s + 128 * 129;       // [k][e] : 128*32
    float* h_s = qn_s + 128 * 32;        // [32][128]
    float* sb_s = h_s + 32 * 128;        // [128]
    float* hs_s = sb_s + 128;            // [8 warps][128]

    int bx = blockIdx.x;
    int b = bx / 48, rem = bx % 48;
    int m = rem / 16, n0 = (rem % 16) * 32;
    int tid = threadIdx.x, w = tid >> 5, lane = tid & 31;

    for (int idx = tid; idx < 16384; idx += 256) {
        int k = idx >> 7, d = idx & 127;
        W_s[k * 129 + d] = spW[m * 16384 + idx];
    }
    for (int idx = tid; idx < 4096; idx += 256) {
        int e = idx >> 7, d = idx & 127;
        qn_s[d * 32 + e] = g_qn[m * 4096 + idx];
    }
    for (int idx = tid; idx < 32 * 128; idx += 256)
        h_s[idx] = g_H[(b * 512 + n0) * 128 + idx];
    if (tid < 128) sb_s[tid] = spb[m * 128 + tid];
    __syncthreads();

    for (int nn = w; nn < 32; nn += 8) {
        const float* hrow = h_s + nn * 128;
        float hsk[4];
#pragma unroll
        for (int q = 0; q < 4; q++) hsk[q] = sb_s[lane + 32 * q];
        for (int d = 0; d < 128; d++) {
            float hv = hrow[d];
#pragma unroll
            for (int q = 0; q < 4; q++)
                hsk[q] = fmaf(W_s[(lane + 32 * q) * 129 + d], hv, hsk[q]);
        }
        float sq = hsk[0] * hsk[0] + hsk[1] * hsk[1] + hsk[2] * hsk[2] + hsk[3] * hsk[3];
        sq = warp_sum(sq);
        float inv = 1.0f / fmaxf(sqrtf(sq), 1e-12f);
#pragma unroll
        for (int q = 0; q < 4; q++) hs_s[w * 128 + lane + 32 * q] = hsk[q] * inv;
        __syncwarp();

        float acc = 0.f;
        for (int k = 0; k < 128; k++)
            acc = fmaf(hs_s[w * 128 + k], qn_s[k * 32 + lane], acc);
        g_scores[((b * 3 + m) * 32 + lane) * 512 + n0 + nn] = acc;
        __syncwarp();
    }
}

// ---------------- K6: top-25 over n + softmax(T=0.7) + Hmix accumulation ----------
__global__ void k_topk() {
    int tid = threadIdx.x, w = tid >> 5, lane = tid & 31;
    int row = blockIdx.x * 8 + w;         // 768 rows = [b][m][e]
    int b = row / 96, m = (row / 32) % 3, e = row % 32;
    const float* sc = g_scores + row * 512;

    float v[16];
#pragma unroll
    for (int j = 0; j < 16; j++) v[j] = sc[lane + j * 32];

    float topv[KTOP];
    int topi[KTOP];
    for (int it = 0; it < KTOP; it++) {
        float bv = -FLT_MAX;
        int bi = 0x7FFFFFFF;
#pragma unroll
        for (int j = 0; j < 16; j++) {
            if (v[j] > bv) { bv = v[j]; bi = lane + j * 32; }
        }
#pragma unroll
        for (int off = 16; off; off >>= 1) {
            float ov = __shfl_xor_sync(0xFFFFFFFFu, bv, off);
            int oi = __shfl_xor_sync(0xFFFFFFFFu, bi, off);
            if (ov > bv || (ov == bv && oi < bi)) { bv = ov; bi = oi; }
        }
        topv[it] = bv;
        topi[it] = bi;
#pragma unroll
        for (int j = 0; j < 16; j++)
            if (lane + j * 32 == bi) v[j] = -FLT_MAX;
    }

    if (lane == 0) {
        float vmax = topv[0];
        float ssum = 0.f;
        float wexp[KTOP];
        const float itau = 1.0f / 0.7f;
        for (int i = 0; i < KTOP; i++) {
            wexp[i] = __expf((topv[i] - vmax) * itau);
            ssum += wexp[i];
        }
        float pm = g_probs[b * 3 + m] / ssum;
        float* hm = g_Hmix + (b * 32 + e) * 512;
        for (int i = 0; i < KTOP; i++) atomicAdd(&hm[topi[i]], pm * wexp[i]);
    }
}

// ---------------- K7: ew = Hmix@hw ; out = a*zpw + (1-a)*Hmix^T@ew + out_b --------
__global__ void k_final(const float* __restrict__ plog, const float* __restrict__ outb,
                        float* __restrict__ dout) {
    int b = blockIdx.x, tid = threadIdx.x, w = tid >> 5, lane = tid & 31;
    __shared__ float hwsm[512], ewsm[32];
    for (int j = tid; j < 512; j += 256) hwsm[j] = g_hw[b * 512 + j];
    __syncthreads();
#pragma unroll
    for (int ei = 0; ei < 4; ei++) {
        int e = w + ei * 8;
        float acc = 0.f;
        const float* hm = g_Hmix + (b * 32 + e) * 512;
        for (int n = lane; n < 512; n += 32) acc = fmaf(hm[n], hwsm[n], acc);
        acc = warp_sum(acc);
        if (lane == 0) ewsm[e] = acc;
    }
    __syncthreads();
    float alpha = sigm(plog[0]);
    float ob = outb[0];
    for (int n = tid; n < 512; n += 256) {
        float acc = 0.f;
#pragma unroll 8
        for (int e = 0; e < 32; e++)
            acc = fmaf(g_Hmix[(b * 32 + e) * 512 + n], ewsm[e], acc);
        dout[b * 512 + n] = fmaf(alpha, g_zpw[b * 512 + n] - acc, acc) + ob;
    }
}

// ---------------- launch ----------------
extern "C" void kernel_launch(void* const* d_in, const int* in_sizes, int n_in,
                              void* d_out, int out_size) {
    const float* x     = (const float*)d_in[0];
    const float* prior = (const float*)d_in[1];
    const float* pW    = (const float*)d_in[2];
    const float* pb    = (const float*)d_in[3];
    const float* Wih   = (const float*)d_in[4];
    const float* Whh   = (const float*)d_in[5];
    const float* bih   = (const float*)d_in[6];
    const float* bhh   = (const float*)d_in[7];
    const float* spW   = (const float*)d_in[8];
    const float* spb   = (const float*)d_in[9];
    const float* rW    = (const float*)d_in[10];
    const float* rb    = (const float*)d_in[11];
    const float* outW  = (const float*)d_in[12];
    const float* outb  = (const float*)d_in[13];
    const float* plog  = (const float*)d_in[14];
    const float* q     = (const float*)d_in[15];
    float* dout = (float*)d_out;

    const int smem_gru =
        (128 * WSTR + 4 + 4096 + 2048 + 384 + 384 + 128) * (int)sizeof(float);  // 226832
    const int smem_sc  = (128 * 129 + 128 * 32 + 32 * 128 + 128 + 8 * 128) * (int)sizeof(float);
    cudaFuncSetAttribute(k_gru, cudaFuncAttributeMaxDynamicSharedMemorySize, smem_gru);
    cudaFuncSetAttribute(k_scores, cudaFuncAttributeMaxDynamicSharedMemorySize, smem_sc);

    k_prep_uv<<<1, 384>>>(Wih, pW, pb, bih);        // idx 0
    k_prep_q<<<3, 256>>>(q);                        // idx 1
    k_zero<<<128, 256>>>();                         // idx 2
    k_gru<<<128, 1024, smem_gru>>>(Whh, bhh, x);    // idx 3  (profile target)
    k_hw_stats<<<128, 256>>>(outW);                 // idx 4
    k_router<<<8, 256>>>(rW, rb, dout);             // idx 5
    k_prior<<<512, 256>>>(prior);                   // idx 6
    k_scores<<<384, 256, smem_sc>>>(spW, spb);      // idx 7
    k_topk<<<96, 256>>>();                          // idx 8
    k_final<<<8, 256>>>(plog, outb, dout);          // idx 9
}

// round 16
// speedup vs baseline: 1.7860x; 1.7860x over previous
#include <cuda_runtime.h>
#include <cuda_bf16.h>
#include <math.h>
#include <float.h>
#include <stdint.h>

// Shapes: B=8, N=512, T=64, D=128, E=32, M=3, k_top=25
#define KTOP 25

// ---------------- scratch (__device__ globals; allocation is forbidden) ----------------
__device__ float g_uv[2 * 384];            // u = W_ih@proj_W ; v = W_ih@proj_b + b_ih
__device__ float g_qn[3 * 32 * 128];       // normalized queries [m][e][d]
__device__ float g_H[4096 * 128];          // final GRU hidden state [b*512+n][d]
__device__ float g_hw[4096];               // h . out_W
__device__ float g_zpw[4096];              // prior @ hw
__device__ float g_part[8 * 16 * 256];     // per-(b,chunk) partial [sum(128) | sumsq(128)]
__device__ float g_probs[8 * 3];
__device__ float g_scores[8 * 3 * 32 * 512];   // [b][m][e][n]
__device__ float g_Hmix[8 * 32 * 512];         // [b][e][n]

// ---------------- generic helpers ----------------
__device__ __forceinline__ float sigm(float x) { return 1.0f / (1.0f + __expf(-x)); }
__device__ __forceinline__ float tanh_f(float x) {
    float t = __expf(-2.0f * x);
    return (1.0f - t) / (1.0f + t);
}
__device__ __forceinline__ float warp_sum(float v) {
#pragma unroll
    for (int off = 16; off; off >>= 1) v += __shfl_xor_sync(0xFFFFFFFFu, v, off);
    return v;
}
__device__ __forceinline__ uint32_t smem_to_u32(const void* p) {
    uint32_t a;
    asm("{ .reg .u64 t; cvta.to.shared.u64 t, %1; cvt.u32.u64 %0, t; }" : "=r"(a) : "l"(p));
    return a;
}
__device__ __forceinline__ uint32_t pack_bf(float a, float b) {
    __nv_bfloat162 p = __floats2bfloat162_rn(a, b);  // x=a (low), y=b (high)
    uint32_t r;
    memcpy(&r, &p, 4);
    return r;
}
__device__ __forceinline__ void ldmx4(uint32_t* r, uint32_t addr) {
    asm volatile("ldmatrix.sync.aligned.m8n8.x4.shared.b16 {%0,%1,%2,%3}, [%4];"
                 : "=r"(r[0]), "=r"(r[1]), "=r"(r[2]), "=r"(r[3]) : "r"(addr));
}
#define MMA_BF16(c, a, b0, b1) \
    asm volatile("mma.sync.aligned.m16n8k16.row.col.f32.bf16.bf16.f32 " \
        "{%0,%1,%2,%3}, {%4,%5,%6,%7}, {%8,%9}, {%0,%1,%2,%3};" \
        : "+f"((c)[0]), "+f"((c)[1]), "+f"((c)[2]), "+f"((c)[3]) \
        : "r"((a)[0]), "r"((a)[1]), "r"((a)[2]), "r"((a)[3]), "r"(b0), "r"(b1))

// ---------------- K0a: u = W_ih@proj_W, v = W_ih@proj_b + b_ih ----------------
__global__ void k_prep_uv(const float* __restrict__ Wih, const float* __restrict__ pW,
                          const float* __restrict__ pb, const float* __restrict__ bih) {
    int tid = threadIdx.x;
    if (tid < 384) {
        float su = 0.f, sv = 0.f;
        for (int d = 0; d < 128; d++) {
            float w = Wih[tid * 128 + d];
            su = fmaf(w, pW[d], su);
            sv = fmaf(w, pb[d], sv);
        }
        g_uv[tid] = su;
        g_uv[384 + tid] = sv + bih[tid];
    }
}

// ---------------- K0b: normalize queries (warp per 4 rows, 96 rows) ----------------
__global__ void k_prep_q(const float* __restrict__ q) {
    int w = threadIdx.x >> 5, lane = threadIdx.x & 31;
#pragma unroll
    for (int rr = 0; rr < 4; rr++) {
        int row = (blockIdx.x * 8 + w) * 4 + rr;  // 0..95
        float4 v = ((const float4*)(q + row * 128))[lane];
        float ss = v.x * v.x + v.y * v.y + v.z * v.z + v.w * v.w;
        ss = warp_sum(ss);
        float inv = 1.0f / fmaxf(sqrtf(ss), 1e-12f);
        float4 o = make_float4(v.x * inv, v.y * inv, v.z * inv, v.w * inv);
        ((float4*)(g_qn + row * 128))[lane] = o;
    }
}

// ---------------- K0c: zero Hmix ----------------
__global__ void k_zero() {
    int base = blockIdx.x * 256 + threadIdx.x;  // grid 128 x 256 = 32768
#pragma unroll
    for (int i = 0; i < 4; i++) g_Hmix[base + i * 32768] = 0.f;
}

// ---------------- K1: GRU on mma.sync bf16 tensor cores ----------------
// 128 CTAs x 384 threads (12 warps), 32 seqs/CTA.
// Step GEMM: C[384,32] = W[384,128] @ h[128,32], 3-term bf16 split:
//   W_hi@B_hi + W_hi@B_lo + W_lo@B_hi   (fp32 accumulate)
// W_hi fragments resident in registers; W_lo in smem (ldmatrix); B=[n][k] bf16
// rows rebuilt per step (= .col operand via non-trans ldmatrix).
#define OFF_WLO 0
#define OFF_BHI 104448
#define OFF_BLO 113152
#define OFF_C   121856
#define OFF_SSH 174080
#define OFF_TAB 182272
#define SMEM_GT 185856
#define CSTR 34

__global__ __launch_bounds__(384, 1)
void k_gru_tc(const float* __restrict__ Whh, const float* __restrict__ bhh,
              const float* __restrict__ x) {
    extern __shared__ char smem[];
    const uint32_t sb = smem_to_u32(smem);
    const int tid = threadIdx.x;
    const int w = tid >> 5, lane = tid & 31;
    const int i0 = blockIdx.x * 32;

    __nv_bfloat16* Wlo = (__nv_bfloat16*)(smem + OFF_WLO);  // [384][136] (272B rows)
    float* Cs = (float*)(smem + OFF_C);                     // [384][34]
    float* ssh = (float*)(smem + OFF_SSH);                  // [t][seq]
    float* tab = (float*)(smem + OFF_TAB);                  // u(384) | c(384) | v_n(128)

    // stage W_lo (bf16 of residual), zero B buffers, stage scalar inputs, tables
    for (int idx = tid; idx < 384 * 128; idx += 384) {
        int r = idx >> 7, k = idx & 127;
        float wv = Whh[idx];
        __nv_bfloat16 hi = __float2bfloat16(wv);
        Wlo[r * 136 + k] = __float2bfloat16(wv - __bfloat162float(hi));
    }
    for (int idx = tid; idx < (8704 * 2) / 4; idx += 384)
        ((uint32_t*)(smem + OFF_BHI))[idx] = 0u;
    for (int idx = tid; idx < 2048; idx += 384) {
        int s = idx >> 6, t = idx & 63;
        int i = i0 + s;
        ssh[t * 32 + s] = x[(i >> 9) * 32768 + ((i & 7) * 64 + t) * 64 + ((i >> 3) & 63)];
    }
    {
        int g = tid >> 7;
        tab[tid] = g_uv[tid];
        tab[384 + tid] = (g < 2) ? (g_uv[384 + tid] + bhh[tid]) : bhh[tid];
        if (tid < 128) tab[768 + tid] = g_uv[384 + 256 + tid];
    }

    // resident W_hi fragments (m16n8k16 A layout, loaded straight from gmem)
    uint32_t wh[2][8][4];
    {
        int g = lane >> 2, t2 = (lane & 3) * 2;
        int mrow = w * 32;
#pragma unroll
        for (int mt = 0; mt < 2; mt++)
#pragma unroll
            for (int kt = 0; kt < 8; kt++) {
                const float* base = Whh + (mrow + 16 * mt + g) * 128 + 16 * kt + t2;
                float2 p0 = *(const float2*)(base);
                float2 p1 = *(const float2*)(base + 8 * 128);
                float2 p2 = *(const float2*)(base + 8);
                float2 p3 = *(const float2*)(base + 8 * 128 + 8);
                wh[mt][kt][0] = pack_bf(p0.x, p0.y);
                wh[mt][kt][1] = pack_bf(p1.x, p1.y);
                wh[mt][kt][2] = pack_bf(p2.x, p2.y);
                wh[mt][kt][3] = pack_bf(p3.x, p3.y);
            }
    }
    __syncthreads();

    // epilogue mapping: fixed d per thread, 3 seq-groups
    const int ed = tid & 127, egrp = tid >> 7;
    const int es0 = egrp * 11;
    const int ecnt = (egrp < 2) ? 11 : 10;
    const float u_r = tab[ed], u_z = tab[128 + ed], u_n = tab[256 + ed];
    const float c_r = tab[384 + ed], c_z = tab[512 + ed];
    const float bh_n = tab[640 + ed], v_n = tab[768 + ed];
    float h[11];
#pragma unroll
    for (int q = 0; q < 11; q++) h[q] = 0.f;

    // ldmatrix per-lane offsets
    const uint32_t aoff = sb + OFF_WLO +
        (uint32_t)((w * 32 + (lane & 15)) * 272 + (lane >> 4) * 16);
    const uint32_t bofs =
        (uint32_t)((8 * (lane >> 4) + (lane & 7)) * 272 + ((lane >> 3) & 1) * 16);
    const uint32_t bhi0 = sb + OFF_BHI + bofs;
    const uint32_t blo0 = sb + OFF_BLO + bofs;
    const int cg = lane >> 2, ct2 = (lane & 3) * 2;

#pragma unroll 1
    for (int t = 0; t < 64; t++) {
        float acc[2][4][4];
#pragma unroll
        for (int mt = 0; mt < 2; mt++)
#pragma unroll
            for (int nf = 0; nf < 4; nf++)
#pragma unroll
                for (int e = 0; e < 4; e++) acc[mt][nf][e] = 0.f;

#pragma unroll
        for (int kt = 0; kt < 8; kt++) {
            uint32_t bh0[4], bh1[4], bl0[4], bl1[4], al0[4], al1[4];
            ldmx4(bh0, bhi0 + kt * 32);
            ldmx4(bh1, bhi0 + kt * 32 + 16 * 272);
            ldmx4(bl0, blo0 + kt * 32);
            ldmx4(bl1, blo0 + kt * 32 + 16 * 272);
            ldmx4(al0, aoff + kt * 32);
            ldmx4(al1, aoff + kt * 32 + 16 * 272);
#pragma unroll
            for (int mt = 0; mt < 2; mt++) {
                uint32_t* A = wh[mt][kt];
                uint32_t* AL = mt ? al1 : al0;
                MMA_BF16(acc[mt][0], A, bh0[0], bh0[1]);
                MMA_BF16(acc[mt][1], A, bh0[2], bh0[3]);
                MMA_BF16(acc[mt][2], A, bh1[0], bh1[1]);
                MMA_BF16(acc[mt][3], A, bh1[2], bh1[3]);
                MMA_BF16(acc[mt][0], A, bl0[0], bl0[1]);
                MMA_BF16(acc[mt][1], A, bl0[2], bl0[3]);
                MMA_BF16(acc[mt][2], A, bl1[0], bl1[1]);
                MMA_BF16(acc[mt][3], A, bl1[2], bl1[3]);
                MMA_BF16(acc[mt][0], AL, bh0[0], bh0[1]);
                MMA_BF16(acc[mt][1], AL, bh0[2], bh0[3]);
                MMA_BF16(acc[mt][2], AL, bh1[0], bh1[1]);
                MMA_BF16(acc[mt][3], AL, bh1[2], bh1[3]);
            }
        }

        // stage C (fp32) to smem: rows = gate-major output rows, cols = seq
#pragma unroll
        for (int mt = 0; mt < 2; mt++)
#pragma unroll
            for (int nf = 0; nf < 4; nf++) {
                int r = w * 32 + 16 * mt + cg;
                int c = nf * 8 + ct2;
                *(float2*)&Cs[r * CSTR + c] = make_float2(acc[mt][nf][0], acc[mt][nf][1]);
                *(float2*)&Cs[(r + 8) * CSTR + c] = make_float2(acc[mt][nf][2], acc[mt][nf][3]);
            }
        __syncthreads();

        // gate epilogue: fp32, writes next-step B (bf16 hi/lo)
#pragma unroll
        for (int q = 0; q < 11; q++) {
            if (q < ecnt) {
                int seq = es0 + q;
                float s = ssh[t * 32 + seq];
                float gr = Cs[ed * CSTR + seq] + fmaf(s, u_r, c_r);
                float gz = Cs[(128 + ed) * CSTR + seq] + fmaf(s, u_z, c_z);
                float hn = Cs[(256 + ed) * CSTR + seq] + bh_n;
                float gn = fmaf(s, u_n, v_n);
                float r = sigm(gr), z = sigm(gz);
                float ng = tanh_f(fmaf(r, hn, gn));
                float hv = fmaf(z, h[q] - ng, ng);  // (1-z)*ng + z*h
                h[q] = hv;
                __nv_bfloat16 hi = __float2bfloat16(hv);
                __nv_bfloat16 lo = __float2bfloat16(hv - __bfloat162float(hi));
                *(__nv_bfloat16*)(smem + OFF_BHI + seq * 272 + ed * 2) = hi;
                *(__nv_bfloat16*)(smem + OFF_BLO + seq * 272 + ed * 2) = lo;
            }
        }
        __syncthreads();
    }

#pragma unroll
    for (int q = 0; q < 11; q++)
        if (q < ecnt) g_H[(i0 + es0 + q) * 128 + ed] = h[q];
}

// ---------------- K2: hw = h.out_W + partial router stats (grid 8x16) ----------------
__global__ void k_hw_stats(const float* __restrict__ outW) {
    int b = blockIdx.x >> 4, c = blockIdx.x & 15;
    int n0 = c * 32;
    int tid = threadIdx.x, w = tid >> 5, lane = tid & 31;
    __shared__ float ps0[256], ps1[256];

    float4 ow = ((const float4*)outW)[lane];
#pragma unroll
    for (int p = 0; p < 4; p++) {
        int n = n0 + w + 8 * p;
        float4 hv = ((const float4*)(g_H + (b * 512 + n) * 128))[lane];
        float acc = hv.x * ow.x + hv.y * ow.y + hv.z * ow.z + hv.w * ow.w;
        acc = warp_sum(acc);
        if (lane == 0) g_hw[b * 512 + n] = acc;
    }

    int d = tid & 127, half = tid >> 7;
    float s0 = 0.f, s1 = 0.f;
    for (int nn = half * 16; nn < half * 16 + 16; nn++) {
        float v = g_H[(b * 512 + n0 + nn) * 128 + d];
        s0 += v;
        s1 = fmaf(v, v, s1);
    }
    ps0[tid] = s0;
    ps1[tid] = s1;
    __syncthreads();
    if (tid < 128) {
        g_part[(b * 16 + c) * 256 + tid] = ps0[tid] + ps0[tid + 128];
        g_part[(b * 16 + c) * 256 + 128 + tid] = ps1[tid] + ps1[tid + 128];
    }
}

// ---------------- K3: router probs from partials (grid 8) ----------------
__global__ void k_router(const float* __restrict__ rW, const float* __restrict__ rb,
                         float* __restrict__ dout) {
    int b = blockIdx.x, tid = threadIdx.x;
    __shared__ float mean_s[128], sd_s[128], lg[3];
    {
        int d = tid & 127, which = tid >> 7;
        float s = 0.f;
        for (int c = 0; c < 16; c++) s += g_part[(b * 16 + c) * 256 + which * 128 + d];
        if (which == 0) mean_s[d] = s * (1.0f / 512.0f);
        else sd_s[d] = s;  // sumsq (temp)
    }
    __syncthreads();
    if (tid < 128) {
        float mu = mean_s[tid];
        float var = (sd_s[tid] - 512.0f * mu * mu) * (1.0f / 511.0f);
        sd_s[tid] = sqrtf(fmaxf(var, 0.f));
    }
    __syncthreads();
    if (tid < 3) {
        float a = rb[tid];
        for (int k = 0; k < 128; k++) a = fmaf(mean_s[k], rW[tid * 256 + k], a);
        for (int k = 0; k < 128; k++) a = fmaf(sd_s[k], rW[tid * 256 + 128 + k], a);
        lg[tid] = a;
    }
    __syncthreads();
    if (tid == 0) {
        float mx = fmaxf(lg[0], fmaxf(lg[1], lg[2]));
        float e0 = __expf(lg[0] - mx), e1 = __expf(lg[1] - mx), e2 = __expf(lg[2] - mx);
        float inv = 1.0f / (e0 + e1 + e2);
        g_probs[b * 3 + 0] = e0 * inv;
        g_probs[b * 3 + 1] = e1 * inv;
        g_probs[b * 3 + 2] = e2 * inv;
        dout[4096 + b * 3 + 0] = e0 * inv;
        dout[4096 + b * 3 + 1] = e1 * inv;
        dout[4096 + b * 3 + 2] = e2 * inv;
    }
}

// ---------------- K4: zpw[b,n] = sum_j prior[n,j]*hw[b,j] (grid 512) ----------------
__global__ void k_prior(const float* __restrict__ prior) {
    __shared__ float prow[512];
    __shared__ float red[8][8];  // [warp][b]
    int n = blockIdx.x, tid = threadIdx.x, w = tid >> 5, lane = tid & 31;
    for (int j = tid; j < 512; j += 256) prow[j] = prior[n * 512 + j];
    __syncthreads();
    int j0 = tid * 2;
    float p0 = prow[j0], p1 = prow[j0 + 1];
#pragma unroll
    for (int b = 0; b < 8; b++) {
        float acc = p0 * g_hw[b * 512 + j0] + p1 * g_hw[b * 512 + j0 + 1];
        acc = warp_sum(acc);
        if (lane == 0) red[w][b] = acc;
    }
    __syncthreads();
    if (tid < 8) {
        float s = 0.f;
#pragma unroll
        for (int ww = 0; ww < 8; ww++) s += red[ww][tid];
        g_zpw[tid * 512 + n] = s;
    }
}

// ---------------- K5: scores[b,m,e,n] = norm(h@spW[m]^T + spb[m]) . qn[m,e] --------
__global__ __launch_bounds__(256) void k_scores(const float* __restrict__ spW,
                                                const float* __restrict__ spb) {
    extern __shared__ float sm4[];
    float* W_s = sm4;                    // [128][129]
    float* qn_s = W_s + 128 * 129;       // [k][e] : 128*32
    float* h_s = qn_s + 128 * 32;        // [32][128]
    float* sb_s = h_s + 32 * 128;        // [128]
    float* hs_s = sb_s + 128;            // [8 warps][128]

    int bx = blockIdx.x;
    int b = bx / 48, rem = bx % 48;
    int m = rem / 16, n0 = (rem % 16) * 32;
    int tid = threadIdx.x, w = tid >> 5, lane = tid & 31;

    for (int idx = tid; idx < 16384; idx += 256) {
        int k = idx >> 7, d = idx & 127;
        W_s[k * 129 + d] = spW[m * 16384 + idx];
    }
    for (int idx = tid; idx < 4096; idx += 256) {
        int e = idx >> 7, d = idx & 127;
        qn_s[d * 32 + e] = g_qn[m * 4096 + idx];
    }
    for (int idx = tid; idx < 32 * 128; idx += 256)
        h_s[idx] = g_H[(b * 512 + n0) * 128 + idx];
    if (tid < 128) sb_s[tid] = spb[m * 128 + tid];
    __syncthreads();

    for (int nn = w; nn < 32; nn += 8) {
        const float* hrow = h_s + nn * 128;
        float hsk[4];
#pragma unroll
        for (int q = 0; q < 4; q++) hsk[q] = sb_s[lane + 32 * q];
        for (int d = 0; d < 128; d++) {
            float hv = hrow[d];
#pragma unroll
            for (int q = 0; q < 4; q++)
                hsk[q] = fmaf(W_s[(lane + 32 * q) * 129 + d], hv, hsk[q]);
        }
        float sq = hsk[0] * hsk[0] + hsk[1] * hsk[1] + hsk[2] * hsk[2] + hsk[3] * hsk[3];
        sq = warp_sum(sq);
        float inv = 1.0f / fmaxf(sqrtf(sq), 1e-12f);
#pragma unroll
        for (int q = 0; q < 4; q++) hs_s[w * 128 + lane + 32 * q] = hsk[q] * inv;
        __syncwarp();

        float acc = 0.f;
        for (int k = 0; k < 128; k++)
            acc = fmaf(hs_s[w * 128 + k], qn_s[k * 32 + lane], acc);
        g_scores[((b * 3 + m) * 32 + lane) * 512 + n0 + nn] = acc;
        __syncwarp();
    }
}

// ---------------- K6: top-25 over n + softmax(T=0.7) + Hmix accumulation ----------
__global__ void k_topk() {
    int tid = threadIdx.x, w = tid >> 5, lane = tid & 31;
    int row = blockIdx.x * 8 + w;         // 768 rows = [b][m][e]
    int b = row / 96, m = (row / 32) % 3, e = row % 32;
    const float* sc = g_scores + row * 512;

    float v[16];
#pragma unroll
    for (int j = 0; j < 16; j++) v[j] = sc[lane + j * 32];

    float topv[KTOP];
    int topi[KTOP];
    for (int it = 0; it < KTOP; it++) {
        float bv = -FLT_MAX;
        int bi = 0x7FFFFFFF;
#pragma unroll
        for (int j = 0; j < 16; j++) {
            if (v[j] > bv) { bv = v[j]; bi = lane + j * 32; }
        }
#pragma unroll
        for (int off = 16; off; off >>= 1) {
            float ov = __shfl_xor_sync(0xFFFFFFFFu, bv, off);
            int oi = __shfl_xor_sync(0xFFFFFFFFu, bi, off);
            if (ov > bv || (ov == bv && oi < bi)) { bv = ov; bi = oi; }
        }
        topv[it] = bv;
        topi[it] = bi;
#pragma unroll
        for (int j = 0; j < 16; j++)
            if (lane + j * 32 == bi) v[j] = -FLT_MAX;
    }

    if (lane == 0) {
        float vmax = topv[0];
        float ssum = 0.f;
        float wexp[KTOP];
        const float itau = 1.0f / 0.7f;
        for (int i = 0; i < KTOP; i++) {
            wexp[i] = __expf((topv[i] - vmax) * itau);
            ssum += wexp[i];
        }
        float pm = g_probs[b * 3 + m] / ssum;
        float* hm = g_Hmix + (b * 32 + e) * 512;
        for (int i = 0; i < KTOP; i++) atomicAdd(&hm[topi[i]], pm * wexp[i]);
    }
}

// ---------------- K7: ew = Hmix@hw ; out = a*zpw + (1-a)*Hmix^T@ew + out_b --------
__global__ void k_final(const float* __restrict__ plog, const float* __restrict__ outb,
                        float* __restrict__ dout) {
    int b = blockIdx.x, tid = threadIdx.x, w = tid >> 5, lane = tid & 31;
    __shared__ float hwsm[512], ewsm[32];
    for (int j = tid; j < 512; j += 256) hwsm[j] = g_hw[b * 512 + j];
    __syncthreads();
#pragma unroll
    for (int ei = 0; ei < 4; ei++) {
        int e = w + ei * 8;
        float acc = 0.f;
        const float* hm = g_Hmix + (b * 32 + e) * 512;
        for (int n = lane; n < 512; n += 32) acc = fmaf(hm[n], hwsm[n], acc);
        acc = warp_sum(acc);
        if (lane == 0) ewsm[e] = acc;
    }
    __syncthreads();
    float alpha = sigm(plog[0]);
    float ob = outb[0];
    for (int n = tid; n < 512; n += 256) {
        float acc = 0.f;
#pragma unroll 8
        for (int e = 0; e < 32; e++)
            acc = fmaf(g_Hmix[(b * 32 + e) * 512 + n], ewsm[e], acc);
        dout[b * 512 + n] = fmaf(alpha, g_zpw[b * 512 + n] - acc, acc) + ob;
    }
}

// ---------------- launch ----------------
extern "C" void kernel_launch(void* const* d_in, const int* in_sizes, int n_in,
                              void* d_out, int out_size) {
    const float* x     = (const float*)d_in[0];
    const float* prior = (const float*)d_in[1];
    const float* pW    = (const float*)d_in[2];
    const float* pb    = (const float*)d_in[3];
    const float* Wih   = (const float*)d_in[4];
    const float* Whh   = (const float*)d_in[5];
    const float* bih   = (const float*)d_in[6];
    const float* bhh   = (const float*)d_in[7];
    const float* spW   = (const float*)d_in[8];
    const float* spb   = (const float*)d_in[9];
    const float* rW    = (const float*)d_in[10];
    const float* rb    = (const float*)d_in[11];
    const float* outW  = (const float*)d_in[12];
    const float* outb  = (const float*)d_in[13];
    const float* plog  = (const float*)d_in[14];
    const float* q     = (const float*)d_in[15];
    float* dout = (float*)d_out;

    const int smem_sc = (128 * 129 + 128 * 32 + 32 * 128 + 128 + 8 * 128) * (int)sizeof(float);
    cudaFuncSetAttribute(k_gru_tc, cudaFuncAttributeMaxDynamicSharedMemorySize, SMEM_GT);
    cudaFuncSetAttribute(k_scores, cudaFuncAttributeMaxDynamicSharedMemorySize, smem_sc);

    k_prep_uv<<<1, 384>>>(Wih, pW, pb, bih);           // idx 0
    k_prep_q<<<3, 256>>>(q);                           // idx 1
    k_zero<<<128, 256>>>();                            // idx 2
    k_gru_tc<<<128, 384, SMEM_GT>>>(Whh, bhh, x);      // idx 3  (profile target)
    k_hw_stats<<<128, 256>>>(outW);                    // idx 4
    k_router<<<8, 256>>>(rW, rb, dout);                // idx 5
    k_prior<<<512, 256>>>(prior);                      // idx 6
    k_scores<<<384, 256, smem_sc>>>(spW, spb);         // idx 7
    k_topk<<<96, 256>>>();                             // idx 8
    k_final<<<8, 256>>>(plog, outb, dout);             // idx 9
}

// round 17
// speedup vs baseline: 2.0190x; 1.1304x over previous
#include <cuda_runtime.h>
#include <cuda_bf16.h>
#include <math.h>
#include <float.h>
#include <stdint.h>

// Shapes: B=8, N=512, T=64, D=128, E=32, M=3, k_top=25
#define KTOP 25

// ---------------- scratch (__device__ globals; allocation is forbidden) ----------------
__device__ float g_uv[2 * 384];            // u = W_ih@proj_W ; v = W_ih@proj_b + b_ih
__device__ float g_qn[3 * 32 * 128];       // normalized queries [m][e][d]
__device__ float g_H[4096 * 128];          // final GRU hidden state [b*512+n][d]
__device__ float g_hw[4096];               // h . out_W
__device__ float g_zpw[4096];              // prior @ hw
__device__ float g_part[8 * 16 * 256];     // per-(b,chunk) partial [sum(128) | sumsq(128)]
__device__ float g_probs[8 * 3];
__device__ float g_scores[8 * 3 * 32 * 512];   // [b][m][e][n]
__device__ float g_Hmix[8 * 32 * 512];         // [b][e][n]

// ---------------- generic helpers ----------------
__device__ __forceinline__ float sigm(float x) { return 1.0f / (1.0f + __expf(-x)); }
__device__ __forceinline__ float tanh_f(float x) {
    float t = __expf(-2.0f * x);
    return (1.0f - t) / (1.0f + t);
}
__device__ __forceinline__ float warp_sum(float v) {
#pragma unroll
    for (int off = 16; off; off >>= 1) v += __shfl_xor_sync(0xFFFFFFFFu, v, off);
    return v;
}
__device__ __forceinline__ uint32_t smem_to_u32(const void* p) {
    uint32_t a;
    asm("{ .reg .u64 t; cvta.to.shared.u64 t, %1; cvt.u32.u64 %0, t; }" : "=r"(a) : "l"(p));
    return a;
}
__device__ __forceinline__ uint32_t pack_bf(float a, float b) {
    __nv_bfloat162 p = __floats2bfloat162_rn(a, b);  // x=a (low), y=b (high)
    uint32_t r;
    memcpy(&r, &p, 4);
    return r;
}
__device__ __forceinline__ void ldmx4(uint32_t* r, uint32_t addr) {
    asm volatile("ldmatrix.sync.aligned.m8n8.x4.shared.b16 {%0,%1,%2,%3}, [%4];"
                 : "=r"(r[0]), "=r"(r[1]), "=r"(r[2]), "=r"(r[3]) : "r"(addr));
}
#define MMA_BF16(c, a, b0, b1) \
    asm volatile("mma.sync.aligned.m16n8k16.row.col.f32.bf16.bf16.f32 " \
        "{%0,%1,%2,%3}, {%4,%5,%6,%7}, {%8,%9}, {%0,%1,%2,%3};" \
        : "+f"((c)[0]), "+f"((c)[1]), "+f"((c)[2]), "+f"((c)[3]) \
        : "r"((a)[0]), "r"((a)[1]), "r"((a)[2]), "r"((a)[3]), "r"(b0), "r"(b1))

// ---------------- K0: fused init (u,v | normalized queries | zero Hmix) ----------
__global__ void k_init(const float* __restrict__ Wih, const float* __restrict__ pW,
                       const float* __restrict__ pb, const float* __restrict__ bih,
                       const float* __restrict__ q) {
    int bx = blockIdx.x, tid = threadIdx.x;
    if (bx == 0) {
        for (int r = tid; r < 384; r += 256) {
            float su = 0.f, sv = 0.f;
            for (int d = 0; d < 128; d++) {
                float w = Wih[r * 128 + d];
                su = fmaf(w, pW[d], su);
                sv = fmaf(w, pb[d], sv);
            }
            g_uv[r] = su;
            g_uv[384 + r] = sv + bih[r];
        }
    } else if (bx <= 3) {
        int w = tid >> 5, lane = tid & 31;
#pragma unroll
        for (int rr = 0; rr < 4; rr++) {
            int row = ((bx - 1) * 8 + w) * 4 + rr;  // 0..95
            float4 v = ((const float4*)(q + row * 128))[lane];
            float ss = v.x * v.x + v.y * v.y + v.z * v.z + v.w * v.w;
            ss = warp_sum(ss);
            float inv = 1.0f / fmaxf(sqrtf(ss), 1e-12f);
            ((float4*)(g_qn + row * 128))[lane] =
                make_float4(v.x * inv, v.y * inv, v.z * inv, v.w * inv);
        }
    } else {
        int base = (bx - 4) * 256 + tid;  // 128 blocks x 256
#pragma unroll
        for (int i = 0; i < 4; i++) g_Hmix[base + i * 32768] = 0.f;
    }
}

// ---------------- K1: GRU on mma.sync bf16 tensor cores (24 warps) ----------------
// 128 CTAs x 768 threads, 32 seqs/CTA. Step GEMM: C[384,32] = W[384,128]@h[128,32],
// 3-term bf16 split (W_hi@B_hi + W_hi@B_lo + W_lo@B_hi, fp32 accum).
// Warp w owns a 16-row M-tile; W_hi fragments register-resident; W_lo + B via
// ldmatrix from smem; C staged fp32 to smem; gate epilogue over all 768 threads.
#define OFF_WLO 0
#define OFF_BHI 104448
#define OFF_BLO 113152
#define OFF_C   121856
#define OFF_SSH 174080
#define OFF_TAB 182272
#define SMEM_GT 185856
#define CSTR 34

__global__ __launch_bounds__(768, 1)
void k_gru_tc(const float* __restrict__ Whh, const float* __restrict__ bhh,
              const float* __restrict__ x) {
    extern __shared__ char smem[];
    const uint32_t sb = smem_to_u32(smem);
    const int tid = threadIdx.x;
    const int w = tid >> 5, lane = tid & 31;
    const int i0 = blockIdx.x * 32;

    __nv_bfloat16* Wlo = (__nv_bfloat16*)(smem + OFF_WLO);  // [384][136] (272B rows)
    float* Cs = (float*)(smem + OFF_C);                     // [384][34]
    float* ssh = (float*)(smem + OFF_SSH);                  // [t][seq]
    float* tab = (float*)(smem + OFF_TAB);                  // u(384) | c(384) | v_n(128)

    // stage W_lo (bf16 residual), zero B buffers, stage scalar inputs, tables
    for (int idx = tid; idx < 384 * 128; idx += 768) {
        int r = idx >> 7, k = idx & 127;
        float wv = Whh[idx];
        __nv_bfloat16 hi = __float2bfloat16(wv);
        Wlo[r * 136 + k] = __float2bfloat16(wv - __bfloat162float(hi));
    }
    for (int idx = tid; idx < (8704 * 2) / 4; idx += 768)
        ((uint32_t*)(smem + OFF_BHI))[idx] = 0u;
    for (int idx = tid; idx < 2048; idx += 768) {
        int s = idx >> 6, t = idx & 63;
        int i = i0 + s;
        ssh[t * 32 + s] = x[(i >> 9) * 32768 + ((i & 7) * 64 + t) * 64 + ((i >> 3) & 63)];
    }
    if (tid < 384) {
        int g = tid >> 7;
        tab[tid] = g_uv[tid];
        tab[384 + tid] = (g < 2) ? (g_uv[384 + tid] + bhh[tid]) : bhh[tid];
        if (tid < 128) tab[768 + tid] = g_uv[384 + 256 + tid];
    }

    // resident W_hi fragments for this warp's 16-row tile (m16n8k16 A layout)
    uint32_t wh[8][4];
    {
        int g = lane >> 2, t2 = (lane & 3) * 2;
        int mrow = w * 16;
#pragma unroll
        for (int kt = 0; kt < 8; kt++) {
            const float* base = Whh + (mrow + g) * 128 + 16 * kt + t2;
            float2 p0 = *(const float2*)(base);
            float2 p1 = *(const float2*)(base + 8 * 128);
            float2 p2 = *(const float2*)(base + 8);
            float2 p3 = *(const float2*)(base + 8 * 128 + 8);
            wh[kt][0] = pack_bf(p0.x, p0.y);
            wh[kt][1] = pack_bf(p1.x, p1.y);
            wh[kt][2] = pack_bf(p2.x, p2.y);
            wh[kt][3] = pack_bf(p3.x, p3.y);
        }
    }
    __syncthreads();

    // epilogue mapping: fixed d per thread, 6 seq-groups {6,6,5,5,5,5}
    const int ed = tid & 127, egrp = tid >> 7;
    const int es0 = (egrp < 2) ? egrp * 6 : 12 + (egrp - 2) * 5;
    const int ecnt = (egrp < 2) ? 6 : 5;
    const float u_r = tab[ed], u_z = tab[128 + ed], u_n = tab[256 + ed];
    const float c_r = tab[384 + ed], c_z = tab[512 + ed];
    const float bh_n = tab[640 + ed], v_n = tab[768 + ed];
    float h[6];
#pragma unroll
    for (int q = 0; q < 6; q++) h[q] = 0.f;

    // ldmatrix per-lane offsets
    const uint32_t aoff = sb + OFF_WLO +
        (uint32_t)((w * 16 + (lane & 15)) * 272 + (lane >> 4) * 16);
    const uint32_t bofs =
        (uint32_t)((8 * (lane >> 4) + (lane & 7)) * 272 + ((lane >> 3) & 1) * 16);
    const uint32_t bhi0 = sb + OFF_BHI + bofs;
    const uint32_t blo0 = sb + OFF_BLO + bofs;
    const int cg = lane >> 2, ct2 = (lane & 3) * 2;

#pragma unroll 1
    for (int t = 0; t < 64; t++) {
        float acc[4][4];
#pragma unroll
        for (int nf = 0; nf < 4; nf++)
#pragma unroll
            for (int e = 0; e < 4; e++) acc[nf][e] = 0.f;

#pragma unroll
        for (int kt = 0; kt < 8; kt++) {
            uint32_t bh0[4], bh1[4], bl0[4], bl1[4], al[4];
            ldmx4(bh0, bhi0 + kt * 32);
            ldmx4(bh1, bhi0 + kt * 32 + 16 * 272);
            ldmx4(bl0, blo0 + kt * 32);
            ldmx4(bl1, blo0 + kt * 32 + 16 * 272);
            ldmx4(al, aoff + kt * 32);
            uint32_t* A = wh[kt];
            MMA_BF16(acc[0], A, bh0[0], bh0[1]);
            MMA_BF16(acc[1], A, bh0[2], bh0[3]);
            MMA_BF16(acc[2], A, bh1[0], bh1[1]);
            MMA_BF16(acc[3], A, bh1[2], bh1[3]);
            MMA_BF16(acc[0], A, bl0[0], bl0[1]);
            MMA_BF16(acc[1], A, bl0[2], bl0[3]);
            MMA_BF16(acc[2], A, bl1[0], bl1[1]);
            MMA_BF16(acc[3], A, bl1[2], bl1[3]);
            MMA_BF16(acc[0], al, bh0[0], bh0[1]);
            MMA_BF16(acc[1], al, bh0[2], bh0[3]);
            MMA_BF16(acc[2], al, bh1[0], bh1[1]);
            MMA_BF16(acc[3], al, bh1[2], bh1[3]);
        }

        // stage C (fp32) to smem: rows = gate-major output rows, cols = seq
#pragma unroll
        for (int nf = 0; nf < 4; nf++) {
            int r = w * 16 + cg;
            int c = nf * 8 + ct2;
            *(float2*)&Cs[r * CSTR + c] = make_float2(acc[nf][0], acc[nf][1]);
            *(float2*)&Cs[(r + 8) * CSTR + c] = make_float2(acc[nf][2], acc[nf][3]);
        }
        __syncthreads();

        // gate epilogue: fp32, writes next-step B (bf16 hi/lo)
#pragma unroll
        for (int q = 0; q < 6; q++) {
            if (q < ecnt) {
                int seq = es0 + q;
                float s = ssh[t * 32 + seq];
                float gr = Cs[ed * CSTR + seq] + fmaf(s, u_r, c_r);
                float gz = Cs[(128 + ed) * CSTR + seq] + fmaf(s, u_z, c_z);
                float hn = Cs[(256 + ed) * CSTR + seq] + bh_n;
                float gn = fmaf(s, u_n, v_n);
                float r = sigm(gr), z = sigm(gz);
                float ng = tanh_f(fmaf(r, hn, gn));
                float hv = fmaf(z, h[q] - ng, ng);  // (1-z)*ng + z*h
                h[q] = hv;
                __nv_bfloat16 hi = __float2bfloat16(hv);
                __nv_bfloat16 lo = __float2bfloat16(hv - __bfloat162float(hi));
                *(__nv_bfloat16*)(smem + OFF_BHI + seq * 272 + ed * 2) = hi;
                *(__nv_bfloat16*)(smem + OFF_BLO + seq * 272 + ed * 2) = lo;
            }
        }
        __syncthreads();
    }

#pragma unroll
    for (int q = 0; q < 6; q++)
        if (q < ecnt) g_H[(i0 + es0 + q) * 128 + ed] = h[q];
}

// ---------------- K2: hw = h.out_W + partial router stats (grid 8x16) ----------------
__global__ void k_hw_stats(const float* __restrict__ outW) {
    int b = blockIdx.x >> 4, c = blockIdx.x & 15;
    int n0 = c * 32;
    int tid = threadIdx.x, w = tid >> 5, lane = tid & 31;
    __shared__ float ps0[256], ps1[256];

    float4 ow = ((const float4*)outW)[lane];
#pragma unroll
    for (int p = 0; p < 4; p++) {
        int n = n0 + w + 8 * p;
        float4 hv = ((const float4*)(g_H + (b * 512 + n) * 128))[lane];
        float acc = hv.x * ow.x + hv.y * ow.y + hv.z * ow.z + hv.w * ow.w;
        acc = warp_sum(acc);
        if (lane == 0) g_hw[b * 512 + n] = acc;
    }

    int d = tid & 127, half = tid >> 7;
    float s0 = 0.f, s1 = 0.f;
    for (int nn = half * 16; nn < half * 16 + 16; nn++) {
        float v = g_H[(b * 512 + n0 + nn) * 128 + d];
        s0 += v;
        s1 = fmaf(v, v, s1);
    }
    ps0[tid] = s0;
    ps1[tid] = s1;
    __syncthreads();
    if (tid < 128) {
        g_part[(b * 16 + c) * 256 + tid] = ps0[tid] + ps0[tid + 128];
        g_part[(b * 16 + c) * 256 + 128 + tid] = ps1[tid] + ps1[tid + 128];
    }
}

// ---------------- K3: router probs from partials (grid 8) ----------------
__global__ void k_router(const float* __restrict__ rW, const float* __restrict__ rb,
                         float* __restrict__ dout) {
    int b = blockIdx.x, tid = threadIdx.x;
    __shared__ float mean_s[128], sd_s[128], lg[3];
    {
        int d = tid & 127, which = tid >> 7;
        float s = 0.f;
        for (int c = 0; c < 16; c++) s += g_part[(b * 16 + c) * 256 + which * 128 + d];
        if (which == 0) mean_s[d] = s * (1.0f / 512.0f);
        else sd_s[d] = s;  // sumsq (temp)
    }
    __syncthreads();
    if (tid < 128) {
        float mu = mean_s[tid];
        float var = (sd_s[tid] - 512.0f * mu * mu) * (1.0f / 511.0f);
        sd_s[tid] = sqrtf(fmaxf(var, 0.f));
    }
    __syncthreads();
    if (tid < 3) {
        float a = rb[tid];
        for (int k = 0; k < 128; k++) a = fmaf(mean_s[k], rW[tid * 256 + k], a);
        for (int k = 0; k < 128; k++) a = fmaf(sd_s[k], rW[tid * 256 + 128 + k], a);
        lg[tid] = a;
    }
    __syncthreads();
    if (tid == 0) {
        float mx = fmaxf(lg[0], fmaxf(lg[1], lg[2]));
        float e0 = __expf(lg[0] - mx), e1 = __expf(lg[1] - mx), e2 = __expf(lg[2] - mx);
        float inv = 1.0f / (e0 + e1 + e2);
        g_probs[b * 3 + 0] = e0 * inv;
        g_probs[b * 3 + 1] = e1 * inv;
        g_probs[b * 3 + 2] = e2 * inv;
        dout[4096 + b * 3 + 0] = e0 * inv;
        dout[4096 + b * 3 + 1] = e1 * inv;
        dout[4096 + b * 3 + 2] = e2 * inv;
    }
}

// ---------------- K4: zpw[b,n] = sum_j prior[n,j]*hw[b,j] (grid 512) ----------------
__global__ void k_prior(const float* __restrict__ prior) {
    __shared__ float prow[512];
    __shared__ float red[8][8];  // [warp][b]
    int n = blockIdx.x, tid = threadIdx.x, w = tid >> 5, lane = tid & 31;
    for (int j = tid; j < 512; j += 256) prow[j] = prior[n * 512 + j];
    __syncthreads();
    int j0 = tid * 2;
    float p0 = prow[j0], p1 = prow[j0 + 1];
#pragma unroll
    for (int b = 0; b < 8; b++) {
        float acc = p0 * g_hw[b * 512 + j0] + p1 * g_hw[b * 512 + j0 + 1];
        acc = warp_sum(acc);
        if (lane == 0) red[w][b] = acc;
    }
    __syncthreads();
    if (tid < 8) {
        float s = 0.f;
#pragma unroll
        for (int ww = 0; ww < 8; ww++) s += red[ww][tid];
        g_zpw[tid * 512 + n] = s;
    }
}

// ---------------- K5: scores[b,m,e,n] = norm(h@spW[m]^T + spb[m]) . qn[m,e] --------
__global__ __launch_bounds__(256) void k_scores(const float* __restrict__ spW,
                                                const float* __restrict__ spb) {
    extern __shared__ float sm4[];
    float* W_s = sm4;                    // [128][129]
    float* qn_s = W_s + 128 * 129;       // [k][e] : 128*32
    float* h_s = qn_s + 128 * 32;        // [32][128]
    float* sb_s = h_s + 32 * 128;        // [128]
    float* hs_s = sb_s + 128;            // [8 warps][128]

    int bx = blockIdx.x;
    int b = bx / 48, rem = bx % 48;
    int m = rem / 16, n0 = (rem % 16) * 32;
    int tid = threadIdx.x, w = tid >> 5, lane = tid & 31;

    for (int idx = tid; idx < 16384; idx += 256) {
        int k = idx >> 7, d = idx & 127;
        W_s[k * 129 + d] = spW[m * 16384 + idx];
    }
    for (int idx = tid; idx < 4096; idx += 256) {
        int e = idx >> 7, d = idx & 127;
        qn_s[d * 32 + e] = g_qn[m * 4096 + idx];
    }
    for (int idx = tid; idx < 32 * 128; idx += 256)
        h_s[idx] = g_H[(b * 512 + n0) * 128 + idx];
    if (tid < 128) sb_s[tid] = spb[m * 128 + tid];
    __syncthreads();

    for (int nn = w; nn < 32; nn += 8) {
        const float* hrow = h_s + nn * 128;
        float hsk[4];
#pragma unroll
        for (int q = 0; q < 4; q++) hsk[q] = sb_s[lane + 32 * q];
        for (int d = 0; d < 128; d++) {
            float hv = hrow[d];
#pragma unroll
            for (int q = 0; q < 4; q++)
                hsk[q] = fmaf(W_s[(lane + 32 * q) * 129 + d], hv, hsk[q]);
        }
        float sq = hsk[0] * hsk[0] + hsk[1] * hsk[1] + hsk[2] * hsk[2] + hsk[3] * hsk[3];
        sq = warp_sum(sq);
        float inv = 1.0f / fmaxf(sqrtf(sq), 1e-12f);
#pragma unroll
        for (int q = 0; q < 4; q++) hs_s[w * 128 + lane + 32 * q] = hsk[q] * inv;
        __syncwarp();

        float acc = 0.f;
        for (int k = 0; k < 128; k++)
            acc = fmaf(hs_s[w * 128 + k], qn_s[k * 32 + lane], acc);
        g_scores[((b * 3 + m) * 32 + lane) * 512 + n0 + nn] = acc;
        __syncwarp();
    }
}

// ---------------- K6: top-25 over n + softmax(T=0.7) + Hmix accumulation ----------
__global__ void k_topk() {
    int tid = threadIdx.x, w = tid >> 5, lane = tid & 31;
    int row = blockIdx.x * 8 + w;         // 768 rows = [b][m][e]
    int b = row / 96, m = (row / 32) % 3, e = row % 32;
    const float* sc = g_scores + row * 512;

    float v[16];
#pragma unroll
    for (int j = 0; j < 16; j++) v[j] = sc[lane + j * 32];

    float topv[KTOP];
    int topi[KTOP];
    for (int it = 0; it < KTOP; it++) {
        float bv = -FLT_MAX;
        int bi = 0x7FFFFFFF;
#pragma unroll
        for (int j = 0; j < 16; j++) {
            if (v[j] > bv) { bv = v[j]; bi = lane + j * 32; }
        }
#pragma unroll
        for (int off = 16; off; off >>= 1) {
            float ov = __shfl_xor_sync(0xFFFFFFFFu, bv, off);
            int oi = __shfl_xor_sync(0xFFFFFFFFu, bi, off);
            if (ov > bv || (ov == bv && oi < bi)) { bv = ov; bi = oi; }
        }
        topv[it] = bv;
        topi[it] = bi;
#pragma unroll
        for (int j = 0; j < 16; j++)
            if (lane + j * 32 == bi) v[j] = -FLT_MAX;
    }

    if (lane == 0) {
        float vmax = topv[0];
        float ssum = 0.f;
        float wexp[KTOP];
        const float itau = 1.0f / 0.7f;
        for (int i = 0; i < KTOP; i++) {
            wexp[i] = __expf((topv[i] - vmax) * itau);
            ssum += wexp[i];
        }
        float pm = g_probs[b * 3 + m] / ssum;
        float* hm = g_Hmix + (b * 32 + e) * 512;
        for (int i = 0; i < KTOP; i++) atomicAdd(&hm[topi[i]], pm * wexp[i]);
    }
}

// ---------------- K7: ew = Hmix@hw ; out = a*zpw + (1-a)*Hmix^T@ew + out_b --------
__global__ void k_final(const float* __restrict__ plog, const float* __restrict__ outb,
                        float* __restrict__ dout) {
    int b = blockIdx.x, tid = threadIdx.x, w = tid >> 5, lane = tid & 31;
    __shared__ float hwsm[512], ewsm[32];
    for (int j = tid; j < 512; j += 256) hwsm[j] = g_hw[b * 512 + j];
    __syncthreads();
#pragma unroll
    for (int ei = 0; ei < 4; ei++) {
        int e = w + ei * 8;
        float acc = 0.f;
        const float* hm = g_Hmix + (b * 32 + e) * 512;
        for (int n = lane; n < 512; n += 32) acc = fmaf(hm[n], hwsm[n], acc);
        acc = warp_sum(acc);
        if (lane == 0) ewsm[e] = acc;
    }
    __syncthreads();
    float alpha = sigm(plog[0]);
    float ob = outb[0];
    for (int n = tid; n < 512; n += 256) {
        float acc = 0.f;
#pragma unroll 8
        for (int e = 0; e < 32; e++)
            acc = fmaf(g_Hmix[(b * 32 + e) * 512 + n], ewsm[e], acc);
        dout[b * 512 + n] = fmaf(alpha, g_zpw[b * 512 + n] - acc, acc) + ob;
    }
}

// ---------------- launch ----------------
extern "C" void kernel_launch(void* const* d_in, const int* in_sizes, int n_in,
                              void* d_out, int out_size) {
    const float* x     = (const float*)d_in[0];
    const float* prior = (const float*)d_in[1];
    const float* pW    = (const float*)d_in[2];
    const float* pb    = (const float*)d_in[3];
    const float* Wih   = (const float*)d_in[4];
    const float* Whh   = (const float*)d_in[5];
    const float* bih   = (const float*)d_in[6];
    const float* bhh   = (const float*)d_in[7];
    const float* spW   = (const float*)d_in[8];
    const float* spb   = (const float*)d_in[9];
    const float* rW    = (const float*)d_in[10];
    const float* rb    = (const float*)d_in[11];
    const float* outW  = (const float*)d_in[12];
    const float* outb  = (const float*)d_in[13];
    const float* plog  = (const float*)d_in[14];
    const float* q     = (const float*)d_in[15];
    float* dout = (float*)d_out;

    const int smem_sc = (128 * 129 + 128 * 32 + 32 * 128 + 128 + 8 * 128) * (int)sizeof(float);
    cudaFuncSetAttribute(k_gru_tc, cudaFuncAttributeMaxDynamicSharedMemorySize, SMEM_GT);
    cudaFuncSetAttribute(k_scores, cudaFuncAttributeMaxDynamicSharedMemorySize, smem_sc);

    k_init<<<132, 256>>>(Wih, pW, pb, bih, q);         // idx 0
    k_gru_tc<<<128, 768, SMEM_GT>>>(Whh, bhh, x);      // idx 1
    k_hw_stats<<<128, 256>>>(outW);                    // idx 2
    k_router<<<8, 256>>>(rW, rb, dout);                // idx 3  (ncu -s 5 target zone)
    k_prior<<<512, 256>>>(prior);                      // idx 4
    k_scores<<<384, 256, smem_sc>>>(spW, spb);         // idx 5
    k_topk<<<96, 256>>>();                             // idx 6
    k_final<<<8, 256>>>(plog, outb, dout);             // idx 7
}